// round 2
// baseline (speedup 1.0000x reference)
#include <cuda_runtime.h>
#include <cuda_bf16.h>

#define FRAME_L   1024
#define HOP       256
#define MAXNF     33024   // >= 32765, padded

// Scratch (no cudaMalloc allowed): per-frame params + hann table.
// g_params[f] = {scale (<0 means invalid/unvoiced), new_len as float}
__device__ float2 g_params[MAXNF];
__device__ float  g_hann[FRAME_L];

__global__ void psola_init_kernel(const float* __restrict__ src_f0,
                                  const float* __restrict__ tgt_f0,
                                  const int* __restrict__ voiced,
                                  int nf)
{
    int i = blockIdx.x * blockDim.x + threadIdx.x;
    if (i < FRAME_L) {
        // hann = 0.5 - 0.5*cos(2*pi*i/L)
        g_hann[i] = 0.5f - 0.5f * cosf(6.28318530717958647692f * (float)i / (float)FRAME_L);
    }
    if (i < nf) {
        float s = src_f0[i];
        float t = tgt_f0[i];
        bool valid = (voiced[i] != 0) && (s >= 1.0f) && (t >= 1.0f);
        float denom = (t >= 1.0f) ? t : 1.0f;
        float ratio = fminf(fmaxf(s / denom, 0.25f), 4.0f);
        // jnp.round is round-half-to-even -> rintf (device default RN mode)
        float nl = fmaxf(1.0f, rintf((float)FRAME_L * ratio));
        float scale = (float)FRAME_L / nl;
        float2 p;
        p.x = valid ? scale : -1.0f;
        p.y = nl;
        g_params[i] = p;
    }
}

// Each thread produces 4 consecutive output samples (aligned float4).
// The 4 samples share the same covering-frame set {fmax-0..fmax-3}.
__global__ void __launch_bounds__(256)
psola_main_kernel(const float* __restrict__ wav,
                  float* __restrict__ out,
                  int T, int nf)
{
    int t4 = (blockIdx.x * blockDim.x + threadIdx.x) << 2;
    if (t4 >= T) return;

    // wav[t] for the 4 samples (needed for unvoiced frames; identity passthrough)
    float4 wt4 = *reinterpret_cast<const float4*>(wav + t4);
    float wt[4] = {wt4.x, wt4.y, wt4.z, wt4.w};

    float acc[4] = {0.f, 0.f, 0.f, 0.f};
    float ws[4]  = {0.f, 0.f, 0.f, 0.f};

    int fmax = t4 >> 8;          // floor(t/HOP)
    int jb   = t4 & 255;         // t mod HOP

    #pragma unroll
    for (int k = 0; k < 4; k++) {
        int f = fmax - k;
        if (f < 0 || f >= nf) continue;

        float2 p = g_params[f];
        const float* __restrict__ fr = wav + (f << 8);   // frame start = f*HOP
        int j0 = jb + (k << 8);                          // local index in [0,1024)
        bool voiced_ok = (p.x >= 0.0f);
        float scale = p.x;
        float nlen  = p.y;

        #pragma unroll
        for (int i = 0; i < 4; i++) {
            int j = j0 + i;
            float h = g_hann[j];
            ws[i] += h;

            float c;
            if (!voiced_ok) {
                // shifted = frames -> frames[f][j] == wav[f*HOP + j] == wav[t]
                c = wt[i];
            } else {
                // x = clip((j+0.5)*scale - 0.5, 0, L-1)
                float x  = fminf(fmaxf(fmaf((float)j + 0.5f, scale, -0.5f), 0.0f),
                                 (float)(FRAME_L - 1));
                float xf = floorf(x);
                int   x0 = (int)xf;
                float w  = x - xf;
                int   x1 = min(x0 + 1, FRAME_L - 1);
                float a  = __ldg(fr + x0);
                float b  = __ldg(fr + x1);
                float v  = a * (1.0f - w) + b * w;
                c = ((float)j < nlen) ? v : 0.0f;
            }
            acc[i] += c * h;
        }
    }

    float4 r;
    r.x = (ws[0] > 1e-8f) ? acc[0] / ws[0] : acc[0];
    r.y = (ws[1] > 1e-8f) ? acc[1] / ws[1] : acc[1];
    r.z = (ws[2] > 1e-8f) ? acc[2] / ws[2] : acc[2];
    r.w = (ws[3] > 1e-8f) ? acc[3] / ws[3] : acc[3];
    *reinterpret_cast<float4*>(out + t4) = r;
}

extern "C" void kernel_launch(void* const* d_in, const int* in_sizes, int n_in,
                              void* d_out, int out_size)
{
    const float* wav    = (const float*)d_in[0];
    const float* src_f0 = (const float*)d_in[1];
    const float* tgt_f0 = (const float*)d_in[2];
    const int*   voiced = (const int*)d_in[3];
    float* out = (float*)d_out;

    int T  = in_sizes[0];
    int nf_cap = (T - FRAME_L) / HOP + 1;
    int nf = in_sizes[1] < nf_cap ? in_sizes[1] : nf_cap;
    if (nf > MAXNF) nf = MAXNF;

    {
        int work = nf > FRAME_L ? nf : FRAME_L;
        int threads = 256;
        int blocks = (work + threads - 1) / threads;
        psola_init_kernel<<<blocks, threads>>>(src_f0, tgt_f0, voiced, nf);
    }
    {
        int threads = 256;
        int n4 = (T + 3) / 4;
        int blocks = (n4 + threads - 1) / threads;
        psola_main_kernel<<<blocks, threads>>>(wav, out, T, nf);
    }
}